// round 8
// baseline (speedup 1.0000x reference)
#include <cuda_runtime.h>
#include <math.h>

#define Bv   4
#define Tv   64
#define Nv   1024
#define Ev   16384
#define Cv   32
#define T1v  62
#define T2v  60

// ---- scratch (device symbols; referenced only from device code) ----
__device__ float g_h1[Bv * T1v * Nv * Cv];    // tconv1 out (normal layout)
__device__ float g_h2[Bv * T2v * Nv * Cv];    // tconv2 out (normal layout)
__device__ float g_xT[Bv * Tv * Cv * Nv];     // x transposed  [b][t][ci][n]
__device__ float g_hcT[Bv * T1v * Cv * Nv];   // cheb out transposed [b][t][ci][n]
__device__ float g_wT[2][3][3072];            // weights [layer][gate][rx*32+co], rx=k*32+ci
__device__ float g_deg[Nv];
__device__ float g_dinv[Nv];
__device__ int   g_cnt[Nv];
__device__ int   g_rowptr[Nv + 1];
__device__ int   g_col[Ev];
__device__ float g_val[Ev];
__device__ int   g_is64;

// ---- f32x2 helpers ----
__device__ __forceinline__ unsigned long long fma2(unsigned long long a,
                                                   unsigned long long b,
                                                   unsigned long long c) {
    unsigned long long d;
    asm("fma.rn.f32x2 %0, %1, %2, %3;" : "=l"(d) : "l"(a), "l"(b), "l"(c));
    return d;
}
__device__ __forceinline__ void unpack2(unsigned long long v, float& lo, float& hi) {
    unsigned a, b;
    asm("mov.b64 {%0, %1}, %2;" : "=r"(a), "=r"(b) : "l"(v));
    lo = __uint_as_float(a);
    hi = __uint_as_float(b);
}

__device__ __forceinline__ void load_edge(const void* ei, int e, int& s, int& d) {
    if (g_is64) {
        const long long* e64 = (const long long*)ei;
        s = (int)e64[e];
        d = (int)e64[Ev + e];
    } else {
        const int* e32 = (const int*)ei;
        s = e32[e];
        d = e32[Ev + e];
    }
}

// ------------------------------------------------------------------
// Prep 1: zero deg/cnt + dtype probe.
// ------------------------------------------------------------------
__global__ void prep_init_kernel(const void* ei) {
    if (blockIdx.x < 4) {
        int i = blockIdx.x * 256 + threadIdx.x;
        g_deg[i] = 0.f;
        g_cnt[i] = 0;
    } else if (threadIdx.x == 0) {
        const int* e32 = (const int*)ei;
        int o = 0;
        for (int i = 1; i < 256; i += 2) o |= e32[i];
        g_is64 = (o == 0) ? 1 : 0;
    }
}

// ------------------------------------------------------------------
// Prep 2 (fat kernel): blocks 0-63 edge deg/cnt; 64-75 weight reshuffle;
// 76.. x transpose -> g_xT  [b][t][ci][n]
// ------------------------------------------------------------------
__global__ void prep_main_kernel(const void* __restrict__ ei,
                                 const float* __restrict__ ew,
                                 const float* __restrict__ x,
                                 const float* __restrict__ w11, const float* __restrict__ w12,
                                 const float* __restrict__ w13, const float* __restrict__ w21,
                                 const float* __restrict__ w22, const float* __restrict__ w23) {
    const int bid = blockIdx.x;
    const int tid = threadIdx.x;
    if (bid < 64) {
        int e = bid * 256 + tid;
        int s, d;
        load_edge(ei, e, s, d);
        if ((unsigned)s >= Nv || (unsigned)d >= Nv) return;
        float w = ew[e];
        if (s != d) atomicAdd(&g_deg[s], w);
        atomicAdd(&g_cnt[d], 1);
    } else if (bid < 76) {
        int i = (bid - 64) * 256 + tid;     // i = rx*32 + co
        if (i >= 3072) return;
        int rx = i >> 5, co = i & 31;
        int k = rx >> 5, ci = rx & 31;
        int s = co * 96 + ci * 3 + k;
        g_wT[0][0][i] = w11[s];
        g_wT[0][1][i] = w12[s];
        g_wT[0][2][i] = w13[s];
        g_wT[1][0][i] = w21[s];
        g_wT[1][1][i] = w22[s];
        g_wT[1][2][i] = w23[s];
    } else {
        // x transpose: 8192 blocks, each a 32n x 32c tile of one (b,t)
        __shared__ float ts[32][33];
        int tb = bid - 76;
        int n0 = (tb & 31) * 32;
        int t  = (tb >> 5) & 63;
        int b  = tb >> 11;
        const float* src = x + ((long long)(b * Tv + t) * Nv + n0) * Cv;
        {
            int n  = tid >> 3;
            int c0 = (tid & 7) * 4;
            float4 v = *(const float4*)(src + n * 32 + c0);
            ts[n][c0]     = v.x;
            ts[n][c0 + 1] = v.y;
            ts[n][c0 + 2] = v.z;
            ts[n][c0 + 3] = v.w;
        }
        __syncthreads();
        {
            int c  = tid >> 3;
            int n4 = (tid & 7) * 4;
            float4 o;
            o.x = ts[n4][c]; o.y = ts[n4 + 1][c];
            o.z = ts[n4 + 2][c]; o.w = ts[n4 + 3][c];
            *(float4*)(g_xT + ((long long)(b * Tv + t) * Cv + c) * Nv + n0 + n4) = o;
        }
    }
}

// ------------------------------------------------------------------
// Prep 3 (single block, 1024 threads): dinv + scan + scatter.
// ------------------------------------------------------------------
__global__ void prep_finish_kernel(const void* __restrict__ ei,
                                   const float* __restrict__ ew) {
    __shared__ int s[Nv];
    __shared__ int offs[Nv];
    int i = threadIdx.x;
    float dg = g_deg[i];
    g_dinv[i] = (dg > 0.f) ? rsqrtf(dg) : 0.f;
    int c = g_cnt[i];
    s[i] = c;
    for (int off = 1; off < Nv; off <<= 1) {
        __syncthreads();
        int v = (i >= off) ? s[i - off] : 0;
        __syncthreads();
        s[i] += v;
    }
    __syncthreads();
    int excl = s[i] - c;
    g_rowptr[i] = excl;
    offs[i]     = excl;
    if (i == Nv - 1) g_rowptr[Nv] = s[i];
    __syncthreads();

    for (int e = i; e < Ev; e += 1024) {
        int src, dst;
        load_edge(ei, e, src, dst);
        if ((unsigned)src >= Nv || (unsigned)dst >= Nv) continue;
        float w = ew[e];
        float nrm = (src == dst) ? 0.f : (-g_dinv[src] * w * g_dinv[dst]);
        int pos = atomicAdd(&offs[dst], 1);
        if ((unsigned)pos < Ev) {
            g_col[pos] = src;
            g_val[pos] = nrm;
        }
    }
}

// ------------------------------------------------------------------
// Temporal gated conv v3.
// Reads transposed activations (g_xT or g_hcT), writes normal layout.
// Block 256 thr, tile 128n x 32co. Warp wg: 4 co; lane: 4 consecutive n.
// Gate-wise outer loop with pre-duplicated f32x2 weights in smem.
// Inner iter: 1 LDS.128 (x, 2 n-pairs) + 2 LDS.128 (w dup, broadcast)
//             + 8 FFMA2. No movs, no swizzle math.
// smem: xs 96*128*4 = 48KB + wsd 96*32*8 = 24KB = 72KB -> 3 CTAs/SM.
// ------------------------------------------------------------------
#define XS_FLOATS (96 * 128)
#define TC_SMEM   (XS_FLOATS * 4 + 96 * 32 * 8)   // 73728 B

__global__ __launch_bounds__(256, 3)
void tconv_kernel(const float* __restrict__ b1, const float* __restrict__ b2,
                  const float* __restrict__ b3,
                  int layer, int src_sel, int dst_sel, int Tin, int Tout)
{
    extern __shared__ __align__(16) float sm[];
    float*  xs  = sm;                                // [rx][n] rx = k*32+ci
    float2* wsd = (float2*)(sm + XS_FLOATS);         // [rx][co] duplicated

    const float* xT  = (src_sel == 0) ? g_xT : g_hcT;
    float*       out = (dst_sel == 0) ? g_h1 : g_h2;

    const int tid = threadIdx.x;
    const int n0  = blockIdx.x * 128;
    const int t   = blockIdx.y;
    const int b   = blockIdx.z;

    // load x tile: straight float4 copy (rows already n-contiguous)
    {
        for (int i4 = tid; i4 < XS_FLOATS / 4; i4 += 256) {
            int rx = i4 >> 5;               // (i4*4)>>7
            int n  = (i4 & 31) * 4;
            int k  = rx >> 5, ci = rx & 31;
            *(float4*)(xs + rx * 128 + n) =
                *(const float4*)(xT + ((long long)(b * Tin + t + k) * Cv + ci) * Nv + n0 + n);
        }
    }

    const int wg   = tid >> 5;
    const int lane = tid & 31;

    unsigned long long acc[3][8];
#pragma unroll
    for (int g = 0; g < 3; ++g)
#pragma unroll
        for (int i = 0; i < 8; ++i) acc[g][i] = 0ull;

#pragma unroll 1
    for (int g = 0; g < 3; ++g) {
        __syncthreads();    // wsd reuse safe (and xs ready on g=0)
        {
            const float* wsg = &g_wT[layer][g][0];
            for (int i = tid; i < 3072; i += 256) {
                float v = wsg[i];
                wsd[i] = make_float2(v, v);
            }
        }
        __syncthreads();

        const float2* wrow = wsd + wg * 4;
        const float*  xrow = xs + lane * 4;
#pragma unroll 8
        for (int rx = 0; rx < 96; ++rx) {
            float4 xv = *(const float4*)(xrow + rx * 128);
            unsigned long long x01 = *(unsigned long long*)&xv.x;
            unsigned long long x23 = *(unsigned long long*)&xv.z;
            ulonglong2 w01 = *(const ulonglong2*)(wrow + rx * 32);
            ulonglong2 w23 = *(const ulonglong2*)(wrow + rx * 32 + 2);
            acc[g][0] = fma2(x01, w01.x, acc[g][0]);
            acc[g][1] = fma2(x01, w01.y, acc[g][1]);
            acc[g][2] = fma2(x01, w23.x, acc[g][2]);
            acc[g][3] = fma2(x01, w23.y, acc[g][3]);
            acc[g][4] = fma2(x23, w01.x, acc[g][4]);
            acc[g][5] = fma2(x23, w01.y, acc[g][5]);
            acc[g][6] = fma2(x23, w23.x, acc[g][6]);
            acc[g][7] = fma2(x23, w23.y, acc[g][7]);
        }
    }
    __syncthreads();   // xs reads done; reuse xs as staging [n][33]

    const int nn = lane * 4;
#pragma unroll
    for (int c = 0; c < 4; ++c) {
        const int co = wg * 4 + c;
        const float bb1 = b1[co], bb2 = b2[co], bb3 = b3[co];
#pragma unroll
        for (int pr = 0; pr < 2; ++pr) {    // n pair: {n0,n1} or {n2,n3}
            float p0, p1, q0, q1, r0, r1;
            unpack2(acc[0][pr * 4 + c], p0, p1);
            unpack2(acc[1][pr * 4 + c], q0, q1);
            unpack2(acc[2][pr * 4 + c], r0, r1);
            p0 += bb1; p1 += bb1;
            q0 += bb2; q1 += bb2;
            r0 += bb3; r1 += bb3;
            float s0 = 1.f / (1.f + __expf(-q0));
            float s1 = 1.f / (1.f + __expf(-q1));
            float h0 = p0 * s0 + r0;
            float h1 = p1 * s1 + r1;
            xs[(nn + pr * 2 + 0) * 33 + co] = (h0 > 0.f) ? h0 : 0.f;
            xs[(nn + pr * 2 + 1) * 33 + co] = (h1 > 0.f) ? h1 : 0.f;
        }
    }
    __syncthreads();

    float* ob = out + ((long long)(b * Tout + t) * Nv + n0) * Cv;
    for (int idx = tid; idx < 4096; idx += 256) {
        ob[idx] = xs[(idx >> 5) * 33 + (idx & 31)];
    }
}

// ------------------------------------------------------------------
// ChebConv K=2 + relu. Warp per node; t-quarter per block.
// Gather unroll x8; GEMM with 4 partial sums. Output written
// TRANSPOSED to g_hcT via smem staging (coalesced 32B rows).
// ------------------------------------------------------------------
__global__ __launch_bounds__(256)
void cheb_kernel(const float* __restrict__ W,      // [2,32,32]
                 const float* __restrict__ bias)   // [32]
{
    __shared__ float Ws[2048];
    __shared__ float cb[32];
    __shared__ float sh[8][32];
    __shared__ float sl[8][32];
    __shared__ float stage[16][32][9];   // [t_local][ch][node_in_block(8), pad]

    const int tid = threadIdx.x;
    for (int i = tid; i < 2048; i += 256) Ws[i] = W[i];
    if (tid < 32) cb[tid] = bias[tid];
    __syncthreads();

    const int w    = tid >> 5;
    const int lane = tid & 31;
    const int tq   = blockIdx.y;
    const int b    = blockIdx.z;
    const int n    = blockIdx.x * 8 + w;

    const int t0     = tq * 16;
    const int tcount = (t0 + 16 <= T1v) ? 16 : (T1v - t0);

    const int e0 = g_rowptr[n], e1 = g_rowptr[n + 1];

    for (int tl = 0; tl < tcount; ++tl) {
        const int t = t0 + tl;
        const float* hb = g_h1 + (long long)((b * T1v + t) * Nv) * Cv;

        float hv = hb[n * 32 + lane];
        float lh = 0.f;
        int e = e0;
        for (; e + 8 <= e1; e += 8) {
            float acc0 = 0.f, acc1 = 0.f;
#pragma unroll
            for (int j = 0; j < 8; j += 2) {
                int   cA = g_col[e + j],     cB = g_col[e + j + 1];
                float vA = g_val[e + j],     vB = g_val[e + j + 1];
                acc0 = fmaf(vA, hb[cA * 32 + lane], acc0);
                acc1 = fmaf(vB, hb[cB * 32 + lane], acc1);
            }
            lh += acc0 + acc1;
        }
        for (; e < e1; ++e) {
            lh = fmaf(g_val[e], hb[g_col[e] * 32 + lane], lh);
        }
        sh[w][lane] = hv;
        sl[w][lane] = lh;
        __syncwarp();

        float o0 = 0.f, o1 = 0.f, o2 = 0.f, o3 = 0.f;
#pragma unroll
        for (int c = 0; c < 8; ++c) {
            o0 = fmaf(sh[w][c],      Ws[c * 32 + lane],          o0);
            o0 = fmaf(sl[w][c],      Ws[1024 + c * 32 + lane],   o0);
            o1 = fmaf(sh[w][c + 8],  Ws[(c + 8) * 32 + lane],    o1);
            o1 = fmaf(sl[w][c + 8],  Ws[1024 + (c + 8) * 32 + lane], o1);
            o2 = fmaf(sh[w][c + 16], Ws[(c + 16) * 32 + lane],   o2);
            o2 = fmaf(sl[w][c + 16], Ws[1024 + (c + 16) * 32 + lane], o2);
            o3 = fmaf(sh[w][c + 24], Ws[(c + 24) * 32 + lane],   o3);
            o3 = fmaf(sl[w][c + 24], Ws[1024 + (c + 24) * 32 + lane], o3);
        }
        float o = cb[lane] + ((o0 + o1) + (o2 + o3));
        o = (o > 0.f) ? o : 0.f;
        stage[tl][lane][w] = o;
        __syncwarp();
    }
    __syncthreads();

    // write transposed: g_hcT[b][t][ch][n0..n0+7] (32B per row)
    const int n0   = blockIdx.x * 8;
    const int rows = tcount * 32;
    for (int r = tid; r < rows; r += 256) {
        int tl = r >> 5, ch = r & 31;
        float4 v0 = make_float4(stage[tl][ch][0], stage[tl][ch][1],
                                stage[tl][ch][2], stage[tl][ch][3]);
        float4 v1 = make_float4(stage[tl][ch][4], stage[tl][ch][5],
                                stage[tl][ch][6], stage[tl][ch][7]);
        float* dst = g_hcT + ((long long)(b * T1v + t0 + tl) * Cv + ch) * Nv + n0;
        *(float4*)dst       = v0;
        *(float4*)(dst + 4) = v1;
    }
}

// ------------------------------------------------------------------
// BatchNorm over (B, T2, C) per node. One block per node. Reads g_h2.
// ------------------------------------------------------------------
__global__ __launch_bounds__(256)
void bn_kernel(const float* __restrict__ gamma,
               const float* __restrict__ beta,
               float* __restrict__ outp)
{
    __shared__ float rs[256], rs2[256];
    __shared__ float s_scale, s_shift;

    const int n   = blockIdx.x;
    const int tid = threadIdx.x;
    const int M   = Bv * T2v * Cv;   // 7680

    float s = 0.f, s2 = 0.f;
    for (int i = tid; i < M; i += 256) {
        int row = i >> 5, c = i & 31;
        float v = g_h2[((long long)row * Nv + n) * 32 + c];
        s += v; s2 += v * v;
    }
    rs[tid] = s; rs2[tid] = s2;
    __syncthreads();
    for (int off = 128; off > 0; off >>= 1) {
        if (tid < off) { rs[tid] += rs[tid + off]; rs2[tid] += rs2[tid + off]; }
        __syncthreads();
    }
    if (tid == 0) {
        float mean = rs[0] / (float)M;
        float var  = rs2[0] / (float)M - mean * mean;
        float rstd = rsqrtf(var + 1e-5f);
        float sc = gamma[n] * rstd;
        s_scale = sc;
        s_shift = beta[n] - mean * sc;
    }
    __syncthreads();
    const float sc = s_scale, sf = s_shift;
    for (int i = tid; i < M; i += 256) {
        int row = i >> 5, c = i & 31;
        long long idx = ((long long)row * Nv + n) * 32 + c;
        outp[idx] = g_h2[idx] * sc + sf;
    }
}

// ------------------------------------------------------------------
extern "C" void kernel_launch(void* const* d_in, const int* in_sizes, int n_in,
                              void* d_out, int out_size)
{
    const float* x   = (const float*)d_in[0];
    const void*  ei  = d_in[1];
    const float* ew  = (const float*)d_in[2];
    const float* w11 = (const float*)d_in[3];
    const float* b11 = (const float*)d_in[4];
    const float* w12 = (const float*)d_in[5];
    const float* b12 = (const float*)d_in[6];
    const float* w13 = (const float*)d_in[7];
    const float* b13 = (const float*)d_in[8];
    const float* cW  = (const float*)d_in[9];
    const float* cb  = (const float*)d_in[10];
    const float* w21 = (const float*)d_in[11];
    const float* b21 = (const float*)d_in[12];
    const float* w22 = (const float*)d_in[13];
    const float* b22 = (const float*)d_in[14];
    const float* w23 = (const float*)d_in[15];
    const float* b23 = (const float*)d_in[16];
    const float* gamma = (const float*)d_in[17];
    const float* beta  = (const float*)d_in[18];
    float* out = (float*)d_out;

    cudaFuncSetAttribute(tconv_kernel,
                         cudaFuncAttributeMaxDynamicSharedMemorySize, TC_SMEM);

    // 1-3: prep (edges, weight reshuffle, x transpose, CSR)
    prep_init_kernel<<<5, 256>>>(ei);
    prep_main_kernel<<<76 + 32 * Tv * Bv, 256>>>(ei, ew, x,
                                                 w11, w12, w13, w21, w22, w23);
    prep_finish_kernel<<<1, 1024>>>(ei, ew);

    // 4: temporal conv 1: g_xT -> g_h1   (ncu capture window)
    {
        dim3 grid(Nv / 128, T1v, Bv);
        tconv_kernel<<<grid, 256, TC_SMEM>>>(b11, b12, b13, 0, 0, 0, Tv, T1v);
    }
    // 5: cheb conv + relu: g_h1 -> g_hcT (transposed)
    {
        dim3 grid(Nv / 8, 4, Bv);
        cheb_kernel<<<grid, 256>>>(cW, cb);
    }
    // 6: temporal conv 2: g_hcT -> g_h2
    {
        dim3 grid(Nv / 128, T2v, Bv);
        tconv_kernel<<<grid, 256, TC_SMEM>>>(b21, b22, b23, 1, 1, 1, T1v, T2v);
    }
    // 7: batch norm per node -> d_out
    bn_kernel<<<Nv, 256>>>(gamma, beta, out);
}

// round 10
// speedup vs baseline: 1.2874x; 1.2874x over previous
#include <cuda_runtime.h>
#include <math.h>

#define Bv   4
#define Tv   64
#define Nv   1024
#define Ev   16384
#define Cv   32
#define T1v  62
#define T2v  60

// ---- device scratch (referenced only from device code) ----
__device__ float g_h1[Bv * T1v * Nv * Cv];
__device__ float g_hc[Bv * T1v * Nv * Cv];
__device__ float g_h2[Bv * T2v * Nv * Cv];
__device__ float g_wT[2][3][3072];     // [layer][gate][r*32+co], r=ci*3+k
__device__ int   g_rowptr[Nv + 1];
__device__ int   g_col[Ev];
__device__ float g_val[Ev];

// ---- f32x2 helpers ----
__device__ __forceinline__ unsigned long long fma2(unsigned long long a,
                                                   unsigned long long b,
                                                   unsigned long long c) {
    unsigned long long d;
    asm("fma.rn.f32x2 %0, %1, %2, %3;" : "=l"(d) : "l"(a), "l"(b), "l"(c));
    return d;
}
__device__ __forceinline__ unsigned long long dup2(float x) {
    unsigned long long d;
    unsigned u = __float_as_uint(x);
    asm("mov.b64 %0, {%1, %1};" : "=l"(d) : "r"(u));
    return d;
}
__device__ __forceinline__ void unpack2(unsigned long long v, float& lo, float& hi) {
    unsigned a, b;
    asm("mov.b64 {%0, %1}, %2;" : "=r"(a), "=r"(b) : "l"(v));
    lo = __uint_as_float(a);
    hi = __uint_as_float(b);
}

__device__ __forceinline__ void load_edge_f(const void* ei, int e, int is64,
                                            int& s, int& d) {
    if (is64) {
        const long long* e64 = (const long long*)ei;
        s = (int)e64[e]; d = (int)e64[Ev + e];
    } else {
        const int* e32 = (const int*)ei;
        s = e32[e]; d = e32[Ev + e];
    }
}

// ------------------------------------------------------------------
// Prep A: weight reshuffle. 12 blocks x 256 = 3072 threads.
// g_wT[layer][g][r*32+co] = w[co*96 + r], r = ci*3+k.
// ------------------------------------------------------------------
__global__ void prep_w_kernel(const float* __restrict__ w11, const float* __restrict__ w12,
                              const float* __restrict__ w13, const float* __restrict__ w21,
                              const float* __restrict__ w22, const float* __restrict__ w23) {
    int i = blockIdx.x * blockDim.x + threadIdx.x;
    if (i >= 3072) return;
    int r = i >> 5, co = i & 31;
    int s = co * 96 + r;
    g_wT[0][0][i] = w11[s];
    g_wT[0][1][i] = w12[s];
    g_wT[0][2][i] = w13[s];
    g_wT[1][0][i] = w21[s];
    g_wT[1][1][i] = w22[s];
    g_wT[1][2][i] = w23[s];
}

// ------------------------------------------------------------------
// Prep B: full graph build in ONE block (1024 threads), smem-resident:
// dtype probe, degree, dinv, count, scan, CSR scatter.
// ------------------------------------------------------------------
__global__ void prep_graph_kernel(const void* __restrict__ ei,
                                  const float* __restrict__ ew) {
    __shared__ float sdeg[Nv];    // degree -> then dinv (in place)
    __shared__ int   scnt[Nv];
    __shared__ int   sscan[Nv];
    __shared__ int   soffs[Nv];
    __shared__ int   sOr;

    const int i = threadIdx.x;
    if (i == 0) sOr = 0;
    sdeg[i] = 0.f;
    scnt[i] = 0;
    __syncthreads();

    // dtype probe: int64 node indices have zero high words at odd int32 slots
    if (i < 128) {
        int v = ((const int*)ei)[2 * i + 1];
        if (v != 0) atomicOr(&sOr, 1);
    }
    __syncthreads();
    const int is64 = (sOr == 0) ? 1 : 0;

    // degree + count (smem atomics)
    for (int e = i; e < Ev; e += 1024) {
        int s, d;
        load_edge_f(ei, e, is64, s, d);
        if ((unsigned)s >= Nv || (unsigned)d >= Nv) continue;
        float w = ew[e];
        if (s != d) atomicAdd(&sdeg[s], w);
        atomicAdd(&scnt[d], 1);
    }
    __syncthreads();

    // dinv in place
    {
        float dg = sdeg[i];
        float dv = (dg > 0.f) ? rsqrtf(dg) : 0.f;
        __syncthreads();
        sdeg[i] = dv;
    }

    // exclusive scan of scnt
    int c = scnt[i];
    sscan[i] = c;
    for (int off = 1; off < Nv; off <<= 1) {
        __syncthreads();
        int v = (i >= off) ? sscan[i - off] : 0;
        __syncthreads();
        sscan[i] += v;
    }
    __syncthreads();
    int excl = sscan[i] - c;
    g_rowptr[i] = excl;
    soffs[i]    = excl;
    if (i == Nv - 1) g_rowptr[Nv] = sscan[i];
    __syncthreads();

    // scatter
    for (int e = i; e < Ev; e += 1024) {
        int s, d;
        load_edge_f(ei, e, is64, s, d);
        if ((unsigned)s >= Nv || (unsigned)d >= Nv) continue;
        float w = ew[e];
        float nrm = (s == d) ? 0.f : (-sdeg[s] * w * sdeg[d]);
        int pos = atomicAdd(&soffs[d], 1);
        if ((unsigned)pos < Ev) {
            g_col[pos] = s;
            g_val[pos] = nrm;
        }
    }
}

// ------------------------------------------------------------------
// Temporal gated conv (proven R7 design, unchanged).
// Block 256 thr, tile 128n x 32co. Warp wg: 4 co; lane: 4 consecutive n.
// f32x2 packed FMA; x tile XOR-swizzled for conflict-free LDS.128.
// ------------------------------------------------------------------
#define WS_FLOATS (3 * 96 * 32)    // 9216
#define XS_FLOATS (3 * 32 * 128)   // 12288
#define TC_SMEM   ((WS_FLOATS + XS_FLOATS) * 4)

__global__ __launch_bounds__(256, 2)
void tconv_kernel(const float* __restrict__ xp,
                  const float* __restrict__ b1, const float* __restrict__ b2,
                  const float* __restrict__ b3,
                  int layer, int src_sel, int dst_sel, int Tin, int Tout)
{
    extern __shared__ __align__(16) float sm[];
    float* ws = sm;
    float* xs = sm + WS_FLOATS;

    const float* x   = (src_sel == 0) ? xp   : (const float*)g_hc;
    float*       out = (dst_sel == 0) ? g_h1 : g_h2;

    const int tid = threadIdx.x;
    const int n0  = blockIdx.x * 128;
    const int t   = blockIdx.y;
    const int b   = blockIdx.z;

    {
        const float* wsrc = &g_wT[layer][0][0];
        for (int i = tid; i < WS_FLOATS; i += 256) ws[i] = wsrc[i];
    }
    {
        const float* xb = x + ((long long)(b * Tin + t) * Nv + n0) * Cv;
        for (int idx = tid; idx < XS_FLOATS; idx += 256) {
            int k   = idx >> 12;
            int rem = idx & 4095;
            int n   = rem >> 5;
            int ci  = rem & 31;
            int rx  = k * 32 + ci;
            xs[rx * 128 + (((n >> 2) ^ ci) << 2) + (n & 3)] =
                xb[(long long)k * Nv * Cv + rem];
        }
    }
    __syncthreads();

    const int wg   = tid >> 5;
    const int lane = tid & 31;

    unsigned long long acc[3][8];
#pragma unroll
    for (int g = 0; g < 3; ++g)
#pragma unroll
        for (int i = 0; i < 8; ++i) acc[g][i] = 0ull;

#pragma unroll 4
    for (int ci = 0; ci < 32; ++ci) {
#pragma unroll
        for (int k = 0; k < 3; ++k) {
            const int rx = k * 32 + ci;
            const float4 xv4 = *(const float4*)(xs + rx * 128 + ((lane ^ ci) << 2));
            unsigned long long xp2[4];
            xp2[0] = dup2(xv4.x); xp2[1] = dup2(xv4.y);
            xp2[2] = dup2(xv4.z); xp2[3] = dup2(xv4.w);
            const int rw = ci * 3 + k;
            const float* wrow = ws + rw * 32 + wg * 4;
#pragma unroll
            for (int g = 0; g < 3; ++g) {
                const ulonglong2 wp = *(const ulonglong2*)(wrow + g * 3072);
#pragma unroll
                for (int i = 0; i < 4; ++i) {
                    acc[g][i * 2 + 0] = fma2(xp2[i], wp.x, acc[g][i * 2 + 0]);
                    acc[g][i * 2 + 1] = fma2(xp2[i], wp.y, acc[g][i * 2 + 1]);
                }
            }
        }
    }
    __syncthreads();

    const int nn = lane * 4;
#pragma unroll
    for (int p = 0; p < 2; ++p) {
        const int co0 = wg * 4 + p * 2;
        const float b1a = b1[co0], b1b = b1[co0 + 1];
        const float b2a = b2[co0], b2b = b2[co0 + 1];
        const float b3a = b3[co0], b3b = b3[co0 + 1];
#pragma unroll
        for (int i = 0; i < 4; ++i) {
            float p0, p1, q0, q1, r0, r1;
            unpack2(acc[0][i * 2 + p], p0, p1);
            unpack2(acc[1][i * 2 + p], q0, q1);
            unpack2(acc[2][i * 2 + p], r0, r1);
            p0 += b1a; p1 += b1b;
            q0 += b2a; q1 += b2b;
            r0 += b3a; r1 += b3b;
            float s0 = 1.f / (1.f + __expf(-q0));
            float s1 = 1.f / (1.f + __expf(-q1));
            float h0 = p0 * s0 + r0;
            float h1 = p1 * s1 + r1;
            xs[(nn + i) * 33 + co0]     = (h0 > 0.f) ? h0 : 0.f;
            xs[(nn + i) * 33 + co0 + 1] = (h1 > 0.f) ? h1 : 0.f;
        }
    }
    __syncthreads();

    float* ob = out + ((long long)(b * Tout + t) * Nv + n0) * Cv;
    for (int idx = tid; idx < 4096; idx += 256) {
        ob[idx] = xs[(idx >> 5) * 33 + (idx & 31)];
    }
}

// ------------------------------------------------------------------
// ChebConv v4: warp per node, 4 t-planes per block (grid.y = 16).
// Per edge: 4 independent gathers across t (MLP 8 with edge-pair unroll).
// GEMM with 4 partial sums.
// ------------------------------------------------------------------
__global__ __launch_bounds__(256)
void cheb_kernel(const float* __restrict__ W, const float* __restrict__ bias)
{
    __shared__ float Ws[2048];
    __shared__ float cb[32];
    __shared__ float sh[8][32];
    __shared__ float sl[8][32];

    const int tid = threadIdx.x;
    for (int i = tid; i < 2048; i += 256) Ws[i] = W[i];
    if (tid < 32) cb[tid] = bias[tid];
    __syncthreads();

    const int w    = tid >> 5;
    const int lane = tid & 31;
    const int b    = blockIdx.z;
    const int n    = blockIdx.x * 8 + w;
    const int t0   = blockIdx.y * 4;
    const int TC   = (t0 + 4 <= T1v) ? 4 : (T1v - t0);   // 4 or 2

    const int e0 = g_rowptr[n], e1 = g_rowptr[n + 1];
    const long long stride = (long long)Nv * Cv;
    const float* base = g_h1 + (long long)(b * T1v + t0) * stride;

    float lh[4] = {0.f, 0.f, 0.f, 0.f};
    float hv[4];
#pragma unroll
    for (int j = 0; j < 4; ++j)
        hv[j] = (j < TC) ? base[j * stride + n * 32 + lane] : 0.f;

    int e = e0;
    for (; e + 2 <= e1; e += 2) {
        int   cA = g_col[e],     cB = g_col[e + 1];
        float vA = g_val[e],     vB = g_val[e + 1];
        const float* pA = base + cA * 32 + lane;
        const float* pB = base + cB * 32 + lane;
#pragma unroll
        for (int j = 0; j < 4; ++j) {
            if (j < TC) {
                lh[j] = fmaf(vA, pA[j * stride], lh[j]);
                lh[j] = fmaf(vB, pB[j * stride], lh[j]);
            }
        }
    }
    if (e < e1) {
        int   cA = g_col[e];
        float vA = g_val[e];
        const float* pA = base + cA * 32 + lane;
#pragma unroll
        for (int j = 0; j < 4; ++j)
            if (j < TC) lh[j] = fmaf(vA, pA[j * stride], lh[j]);
    }

    for (int j = 0; j < TC; ++j) {
        sh[w][lane] = hv[j];
        sl[w][lane] = lh[j];
        __syncwarp();

        float o0 = 0.f, o1 = 0.f, o2 = 0.f, o3 = 0.f;
#pragma unroll
        for (int c = 0; c < 8; ++c) {
            o0 = fmaf(sh[w][c],      Ws[c * 32 + lane],               o0);
            o0 = fmaf(sl[w][c],      Ws[1024 + c * 32 + lane],        o0);
            o1 = fmaf(sh[w][c + 8],  Ws[(c + 8) * 32 + lane],         o1);
            o1 = fmaf(sl[w][c + 8],  Ws[1024 + (c + 8) * 32 + lane],  o1);
            o2 = fmaf(sh[w][c + 16], Ws[(c + 16) * 32 + lane],        o2);
            o2 = fmaf(sl[w][c + 16], Ws[1024 + (c + 16) * 32 + lane], o2);
            o3 = fmaf(sh[w][c + 24], Ws[(c + 24) * 32 + lane],        o3);
            o3 = fmaf(sl[w][c + 24], Ws[1024 + (c + 24) * 32 + lane], o3);
        }
        float o = cb[lane] + ((o0 + o1) + (o2 + o3));
        o = (o > 0.f) ? o : 0.f;
        g_hc[(long long)(b * T1v + t0 + j) * stride + n * 32 + lane] = o;
        __syncwarp();
    }
}

// ------------------------------------------------------------------
// BatchNorm per node over (B, T2, C).
// ------------------------------------------------------------------
__global__ __launch_bounds__(256)
void bn_kernel(const float* __restrict__ gamma, const float* __restrict__ beta,
               float* __restrict__ outp)
{
    __shared__ float rs[256], rs2[256];
    __shared__ float s_scale, s_shift;
    const int n = blockIdx.x, tid = threadIdx.x;
    const int M = Bv * T2v * Cv;

    float s = 0.f, s2 = 0.f;
    for (int i = tid; i < M; i += 256) {
        int row = i >> 5, c = i & 31;
        float v = g_h2[((long long)row * Nv + n) * 32 + c];
        s += v; s2 += v * v;
    }
    rs[tid] = s; rs2[tid] = s2;
    __syncthreads();
    for (int off = 128; off > 0; off >>= 1) {
        if (tid < off) { rs[tid] += rs[tid + off]; rs2[tid] += rs2[tid + off]; }
        __syncthreads();
    }
    if (tid == 0) {
        float mean = rs[0] / (float)M;
        float var  = rs2[0] / (float)M - mean * mean;
        float rstd = rsqrtf(var + 1e-5f);
        float sc = gamma[n] * rstd;
        s_scale = sc;
        s_shift = beta[n] - mean * sc;
    }
    __syncthreads();
    const float sc = s_scale, sf = s_shift;
    for (int i = tid; i < M; i += 256) {
        int row = i >> 5, c = i & 31;
        long long idx = ((long long)row * Nv + n) * 32 + c;
        outp[idx] = g_h2[idx] * sc + sf;
    }
}

// ------------------------------------------------------------------
extern "C" void kernel_launch(void* const* d_in, const int* in_sizes, int n_in,
                              void* d_out, int out_size)
{
    const float* x   = (const float*)d_in[0];
    const void*  ei  = d_in[1];
    const float* ew  = (const float*)d_in[2];
    const float* w11 = (const float*)d_in[3];
    const float* b11 = (const float*)d_in[4];
    const float* w12 = (const float*)d_in[5];
    const float* b12 = (const float*)d_in[6];
    const float* w13 = (const float*)d_in[7];
    const float* b13 = (const float*)d_in[8];
    const float* cW  = (const float*)d_in[9];
    const float* cb  = (const float*)d_in[10];
    const float* w21 = (const float*)d_in[11];
    const float* b21 = (const float*)d_in[12];
    const float* w22 = (const float*)d_in[13];
    const float* b22 = (const float*)d_in[14];
    const float* w23 = (const float*)d_in[15];
    const float* b23 = (const float*)d_in[16];
    const float* gamma = (const float*)d_in[17];
    const float* beta  = (const float*)d_in[18];
    float* out = (float*)d_out;

    cudaFuncSetAttribute(tconv_kernel,
                         cudaFuncAttributeMaxDynamicSharedMemorySize, TC_SMEM);

    // 1: weights   2: graph (single block, smem-resident)
    prep_w_kernel<<<12, 256>>>(w11, w12, w13, w21, w22, w23);
    prep_graph_kernel<<<1, 1024>>>(ei, ew);

    // 3: tconv1
    {
        dim3 grid(Nv / 128, T1v, Bv);
        tconv_kernel<<<grid, 256, TC_SMEM>>>(x, b11, b12, b13, 0, 0, 0, Tv, T1v);
    }
    // 4: cheb (profiling window)
    {
        dim3 grid(Nv / 8, 16, Bv);
        cheb_kernel<<<grid, 256>>>(cW, cb);
    }
    // 5: tconv2
    {
        dim3 grid(Nv / 128, T2v, Bv);
        tconv_kernel<<<grid, 256, TC_SMEM>>>(x, b21, b22, b23, 1, 1, 1, T1v, T2v);
    }
    // 6: bn
    bn_kernel<<<Nv, 256>>>(gamma, beta, out);
}

// round 12
// speedup vs baseline: 1.4057x; 1.0919x over previous
#include <cuda_runtime.h>
#include <math.h>

#define Bv   4
#define Tv   64
#define Nv   1024
#define Ev   16384
#define Cv   32
#define T1v  62
#define T2v  60

// ---- device scratch (referenced only from device code) ----
__device__ float g_h1[Bv * T1v * Nv * Cv];
__device__ float g_hc[Bv * T1v * Nv * Cv];
__device__ float g_h2[Bv * T2v * Nv * Cv];
__device__ float g_y0[Bv * T1v * Nv * Cv];   // h1 @ W0
__device__ float g_y1[Bv * T1v * Nv * Cv];   // h1 @ W1
__device__ float g_wT[2][3][3072];           // [layer][gate][r*32+co], r=ci*3+k
__device__ int   g_rowptr[Nv + 1];
__device__ int   g_col[Ev];
__device__ float g_val[Ev];

// ---- f32x2 helpers ----
__device__ __forceinline__ unsigned long long fma2(unsigned long long a,
                                                   unsigned long long b,
                                                   unsigned long long c) {
    unsigned long long d;
    asm("fma.rn.f32x2 %0, %1, %2, %3;" : "=l"(d) : "l"(a), "l"(b), "l"(c));
    return d;
}
__device__ __forceinline__ unsigned long long dup2(float x) {
    unsigned long long d;
    unsigned u = __float_as_uint(x);
    asm("mov.b64 %0, {%1, %1};" : "=l"(d) : "r"(u));
    return d;
}
__device__ __forceinline__ void unpack2(unsigned long long v, float& lo, float& hi) {
    unsigned a, b;
    asm("mov.b64 {%0, %1}, %2;" : "=r"(a), "=r"(b) : "l"(v));
    lo = __uint_as_float(a);
    hi = __uint_as_float(b);
}

__device__ __forceinline__ void load_edge_f(const void* ei, int e, int is64,
                                            int& s, int& d) {
    if (is64) {
        const long long* e64 = (const long long*)ei;
        s = (int)e64[e]; d = (int)e64[Ev + e];
    } else {
        const int* e32 = (const int*)ei;
        s = e32[e]; d = e32[Ev + e];
    }
}

// ------------------------------------------------------------------
// Prep (single kernel, 4 blocks x 1024):
// blocks 0-2: weight reshuffle (3072 elems); block 3: graph build.
// ------------------------------------------------------------------
__global__ void prep_all_kernel(const void* __restrict__ ei,
                                const float* __restrict__ ew,
                                const float* __restrict__ w11, const float* __restrict__ w12,
                                const float* __restrict__ w13, const float* __restrict__ w21,
                                const float* __restrict__ w22, const float* __restrict__ w23) {
    __shared__ float sdeg[Nv];
    __shared__ int   scnt[Nv];
    __shared__ int   sscan[Nv];
    __shared__ int   soffs[Nv];
    __shared__ int   sOr;

    const int bid = blockIdx.x;
    const int i   = threadIdx.x;

    if (bid < 3) {
        int idx = bid * 1024 + i;
        if (idx < 3072) {
            int r = idx >> 5, co = idx & 31;
            int s = co * 96 + r;
            g_wT[0][0][idx] = w11[s];
            g_wT[0][1][idx] = w12[s];
            g_wT[0][2][idx] = w13[s];
            g_wT[1][0][idx] = w21[s];
            g_wT[1][1][idx] = w22[s];
            g_wT[1][2][idx] = w23[s];
        }
        return;
    }

    // ---- graph build ----
    if (i == 0) sOr = 0;
    sdeg[i] = 0.f;
    scnt[i] = 0;
    __syncthreads();

    if (i < 128) {
        int v = ((const int*)ei)[2 * i + 1];
        if (v != 0) atomicOr(&sOr, 1);
    }
    __syncthreads();
    const int is64 = (sOr == 0) ? 1 : 0;

    for (int e = i; e < Ev; e += 1024) {
        int s, d;
        load_edge_f(ei, e, is64, s, d);
        if ((unsigned)s >= Nv || (unsigned)d >= Nv) continue;
        float w = ew[e];
        if (s != d) atomicAdd(&sdeg[s], w);
        atomicAdd(&scnt[d], 1);
    }
    __syncthreads();

    {
        float dg = sdeg[i];
        float dv = (dg > 0.f) ? rsqrtf(dg) : 0.f;
        __syncthreads();
        sdeg[i] = dv;
    }

    int c = scnt[i];
    sscan[i] = c;
    for (int off = 1; off < Nv; off <<= 1) {
        __syncthreads();
        int v = (i >= off) ? sscan[i - off] : 0;
        __syncthreads();
        sscan[i] += v;
    }
    __syncthreads();
    int excl = sscan[i] - c;
    g_rowptr[i] = excl;
    soffs[i]    = excl;
    if (i == Nv - 1) g_rowptr[Nv] = sscan[i];
    __syncthreads();

    for (int e = i; e < Ev; e += 1024) {
        int s, d;
        load_edge_f(ei, e, is64, s, d);
        if ((unsigned)s >= Nv || (unsigned)d >= Nv) continue;
        float w = ew[e];
        float nrm = (s == d) ? 0.f : (-sdeg[s] * w * sdeg[d]);
        int pos = atomicAdd(&soffs[d], 1);
        if ((unsigned)pos < Ev) {
            g_col[pos] = s;
            g_val[pos] = nrm;
        }
    }
}

// ------------------------------------------------------------------
// Temporal gated conv (proven R7 design, unchanged).
// ------------------------------------------------------------------
#define WS_FLOATS (3 * 96 * 32)    // 9216
#define XS_FLOATS (3 * 32 * 128)   // 12288
#define TC_SMEM   ((WS_FLOATS + XS_FLOATS) * 4)

__global__ __launch_bounds__(256, 2)
void tconv_kernel(const float* __restrict__ xp,
                  const float* __restrict__ b1, const float* __restrict__ b2,
                  const float* __restrict__ b3,
                  int layer, int src_sel, int dst_sel, int Tin, int Tout)
{
    extern __shared__ __align__(16) float sm[];
    float* ws = sm;
    float* xs = sm + WS_FLOATS;

    const float* x   = (src_sel == 0) ? xp   : (const float*)g_hc;
    float*       out = (dst_sel == 0) ? g_h1 : g_h2;

    const int tid = threadIdx.x;
    const int n0  = blockIdx.x * 128;
    const int t   = blockIdx.y;
    const int b   = blockIdx.z;

    {
        const float* wsrc = &g_wT[layer][0][0];
        for (int i = tid; i < WS_FLOATS; i += 256) ws[i] = wsrc[i];
    }
    {
        const float* xb = x + ((long long)(b * Tin + t) * Nv + n0) * Cv;
        for (int idx = tid; idx < XS_FLOATS; idx += 256) {
            int k   = idx >> 12;
            int rem = idx & 4095;
            int n   = rem >> 5;
            int ci  = rem & 31;
            int rx  = k * 32 + ci;
            xs[rx * 128 + (((n >> 2) ^ ci) << 2) + (n & 3)] =
                xb[(long long)k * Nv * Cv + rem];
        }
    }
    __syncthreads();

    const int wg   = tid >> 5;
    const int lane = tid & 31;

    unsigned long long acc[3][8];
#pragma unroll
    for (int g = 0; g < 3; ++g)
#pragma unroll
        for (int i = 0; i < 8; ++i) acc[g][i] = 0ull;

#pragma unroll 4
    for (int ci = 0; ci < 32; ++ci) {
#pragma unroll
        for (int k = 0; k < 3; ++k) {
            const int rx = k * 32 + ci;
            const float4 xv4 = *(const float4*)(xs + rx * 128 + ((lane ^ ci) << 2));
            unsigned long long xp2[4];
            xp2[0] = dup2(xv4.x); xp2[1] = dup2(xv4.y);
            xp2[2] = dup2(xv4.z); xp2[3] = dup2(xv4.w);
            const int rw = ci * 3 + k;
            const float* wrow = ws + rw * 32 + wg * 4;
#pragma unroll
            for (int g = 0; g < 3; ++g) {
                const ulonglong2 wp = *(const ulonglong2*)(wrow + g * 3072);
#pragma unroll
                for (int i = 0; i < 4; ++i) {
                    acc[g][i * 2 + 0] = fma2(xp2[i], wp.x, acc[g][i * 2 + 0]);
                    acc[g][i * 2 + 1] = fma2(xp2[i], wp.y, acc[g][i * 2 + 1]);
                }
            }
        }
    }
    __syncthreads();

    const int nn = lane * 4;
#pragma unroll
    for (int p = 0; p < 2; ++p) {
        const int co0 = wg * 4 + p * 2;
        const float b1a = b1[co0], b1b = b1[co0 + 1];
        const float b2a = b2[co0], b2b = b2[co0 + 1];
        const float b3a = b3[co0], b3b = b3[co0 + 1];
#pragma unroll
        for (int i = 0; i < 4; ++i) {
            float p0, p1, q0, q1, r0, r1;
            unpack2(acc[0][i * 2 + p], p0, p1);
            unpack2(acc[1][i * 2 + p], q0, q1);
            unpack2(acc[2][i * 2 + p], r0, r1);
            p0 += b1a; p1 += b1b;
            q0 += b2a; q1 += b2b;
            r0 += b3a; r1 += b3b;
            float s0 = 1.f / (1.f + __expf(-q0));
            float s1 = 1.f / (1.f + __expf(-q1));
            float h0 = p0 * s0 + r0;
            float h1 = p1 * s1 + r1;
            xs[(nn + i) * 33 + co0]     = (h0 > 0.f) ? h0 : 0.f;
            xs[(nn + i) * 33 + co0 + 1] = (h1 > 0.f) ? h1 : 0.f;
        }
    }
    __syncthreads();

    float* ob = out + ((long long)(b * Tout + t) * Nv + n0) * Cv;
    for (int idx = tid; idx < 4096; idx += 256) {
        ob[idx] = xs[(idx >> 5) * 33 + (idx & 31)];
    }
}

// ------------------------------------------------------------------
// Cheb GEMM: Y0 = h1 @ W0, Y1 = h1 @ W1.
// Tile 128 rows x 64 outs, 256 threads; warp wg: 8 outs; lane: 4 rows.
// Weights PLAIN floats (x is dup'd) -> each acc pair = 2 distinct outs.
// smem: ws [32][64] 8KB | xs [32][128] 16KB; stg [128][66] overlays.
// ------------------------------------------------------------------
#define CG_SMEM 33792

__global__ __launch_bounds__(256)
void cheb_gemm_kernel(const float* __restrict__ W)   // [2][32][32]
{
    extern __shared__ __align__(16) float sm[];
    float* ws = sm;                     // [k][64] plain floats
    float* xs = sm + 2048;              // 4096 floats

    const int tid = threadIdx.x;
    const int n0  = blockIdx.x * 128;
    const int t   = blockIdx.y;
    const int b   = blockIdx.z;

    // ws[k*64+o]: o<32 -> W0[k][o], else W1[k][o-32]   (NOT duplicated)
    for (int i = tid; i < 2048; i += 256) {
        int k = i >> 6, o = i & 63;
        ws[i] = (o < 32) ? W[k * 32 + o] : W[1024 + k * 32 + (o - 32)];
    }
    // x tile transposed with xor swizzle
    {
        const float* xb = g_h1 + ((long long)(b * T1v + t) * Nv + n0) * Cv;
        for (int idx = tid; idx < 4096; idx += 256) {
            int n = idx >> 5, c = idx & 31;
            xs[c * 128 + (((n >> 2) ^ c) << 2) + (n & 3)] = xb[idx];
        }
    }
    __syncthreads();

    const int wg   = tid >> 5;
    const int lane = tid & 31;

    unsigned long long acc[16];
#pragma unroll
    for (int i = 0; i < 16; ++i) acc[i] = 0ull;

#pragma unroll 8
    for (int k = 0; k < 32; ++k) {
        const float4 xv4 = *(const float4*)(xs + k * 128 + ((lane ^ k) << 2));
        unsigned long long xp2[4];
        xp2[0] = dup2(xv4.x); xp2[1] = dup2(xv4.y);
        xp2[2] = dup2(xv4.z); xp2[3] = dup2(xv4.w);
        const float* wrow = ws + k * 64 + wg * 8;
        const ulonglong2 w01 = *(const ulonglong2*)(wrow);      // outs +0..+3
        const ulonglong2 w23 = *(const ulonglong2*)(wrow + 4);  // outs +4..+7
#pragma unroll
        for (int i = 0; i < 4; ++i) {
            acc[i * 4 + 0] = fma2(xp2[i], w01.x, acc[i * 4 + 0]);  // outs +0,+1
            acc[i * 4 + 1] = fma2(xp2[i], w01.y, acc[i * 4 + 1]);  // outs +2,+3
            acc[i * 4 + 2] = fma2(xp2[i], w23.x, acc[i * 4 + 2]);  // outs +4,+5
            acc[i * 4 + 3] = fma2(xp2[i], w23.y, acc[i * 4 + 3]);  // outs +6,+7
        }
    }
    __syncthreads();    // xs/ws reads done; overlay stg

    float* stg = sm;    // [128][66]
    const int nn = lane * 4;
#pragma unroll
    for (int i = 0; i < 4; ++i) {
#pragma unroll
        for (int p = 0; p < 4; ++p) {
            float lo, hi;
            unpack2(acc[i * 4 + p], lo, hi);
            *(float2*)(stg + (nn + i) * 66 + wg * 8 + p * 2) = make_float2(lo, hi);
        }
    }
    __syncthreads();

    const long long base = (long long)(b * T1v + t) * Nv * Cv + (long long)n0 * Cv;
    for (int idx = tid; idx < 4096; idx += 256) {
        int n = idx >> 5, c = idx & 31;
        g_y0[base + idx] = stg[n * 66 + c];
        g_y1[base + idx] = stg[n * 66 + 32 + c];
    }
}

// ------------------------------------------------------------------
// Cheb gather: out = relu(Y0[n] + cb + sum_e norm * Y1[src]).
// Warp per node, 4 t-planes; edge-pair unroll (8 loads in flight).
// ------------------------------------------------------------------
__global__ __launch_bounds__(256)
void cheb_gather_kernel(const float* __restrict__ cbias)
{
    const int tid  = threadIdx.x;
    const int w    = tid >> 5;
    const int lane = tid & 31;
    const int b    = blockIdx.z;
    const int n    = blockIdx.x * 8 + w;
    const int t0   = blockIdx.y * 4;
    const int TC   = (t0 + 4 <= T1v) ? 4 : (T1v - t0);

    const float cb = __ldg(&cbias[lane]);
    const int e0 = g_rowptr[n], e1 = g_rowptr[n + 1];
    const long long stride = (long long)Nv * Cv;
    const float* base1 = g_y1 + (long long)(b * T1v + t0) * stride;
    const float* base0 = g_y0 + (long long)(b * T1v + t0) * stride;

    float lh[4] = {0.f, 0.f, 0.f, 0.f};

    int e = e0;
    for (; e + 2 <= e1; e += 2) {
        int   cA = g_col[e],   cB = g_col[e + 1];
        float vA = g_val[e],   vB = g_val[e + 1];
        const float* pA = base1 + cA * 32 + lane;
        const float* pB = base1 + cB * 32 + lane;
#pragma unroll
        for (int j = 0; j < 4; ++j) {
            if (j < TC) {
                lh[j] = fmaf(vA, pA[j * stride], lh[j]);
                lh[j] = fmaf(vB, pB[j * stride], lh[j]);
            }
        }
    }
    if (e < e1) {
        int   cA = g_col[e];
        float vA = g_val[e];
        const float* pA = base1 + cA * 32 + lane;
#pragma unroll
        for (int j = 0; j < 4; ++j)
            if (j < TC) lh[j] = fmaf(vA, pA[j * stride], lh[j]);
    }

    float* outb = g_hc + (long long)(b * T1v + t0) * stride + n * 32 + lane;
#pragma unroll
    for (int j = 0; j < 4; ++j) {
        if (j < TC) {
            float o = base0[j * stride + n * 32 + lane] + cb + lh[j];
            outb[j * stride] = (o > 0.f) ? o : 0.f;
        }
    }
}

// ------------------------------------------------------------------
// BatchNorm per node over (B, T2, C).
// ------------------------------------------------------------------
__global__ __launch_bounds__(256)
void bn_kernel(const float* __restrict__ gamma, const float* __restrict__ beta,
               float* __restrict__ outp)
{
    __shared__ float rs[256], rs2[256];
    __shared__ float s_scale, s_shift;
    const int n = blockIdx.x, tid = threadIdx.x;
    const int M = Bv * T2v * Cv;

    float s = 0.f, s2 = 0.f;
    for (int i = tid; i < M; i += 256) {
        int row = i >> 5, c = i & 31;
        float v = g_h2[((long long)row * Nv + n) * 32 + c];
        s += v; s2 += v * v;
    }
    rs[tid] = s; rs2[tid] = s2;
    __syncthreads();
    for (int off = 128; off > 0; off >>= 1) {
        if (tid < off) { rs[tid] += rs[tid + off]; rs2[tid] += rs2[tid + off]; }
        __syncthreads();
    }
    if (tid == 0) {
        float mean = rs[0] / (float)M;
        float var  = rs2[0] / (float)M - mean * mean;
        float rstd = rsqrtf(var + 1e-5f);
        float sc = gamma[n] * rstd;
        s_scale = sc;
        s_shift = beta[n] - mean * sc;
    }
    __syncthreads();
    const float sc = s_scale, sf = s_shift;
    for (int i = tid; i < M; i += 256) {
        int row = i >> 5, c = i & 31;
        long long idx = ((long long)row * Nv + n) * 32 + c;
        outp[idx] = g_h2[idx] * sc + sf;
    }
}

// ------------------------------------------------------------------
extern "C" void kernel_launch(void* const* d_in, const int* in_sizes, int n_in,
                              void* d_out, int out_size)
{
    const float* x   = (const float*)d_in[0];
    const void*  ei  = d_in[1];
    const float* ew  = (const float*)d_in[2];
    const float* w11 = (const float*)d_in[3];
    const float* b11 = (const float*)d_in[4];
    const float* w12 = (const float*)d_in[5];
    const float* b12 = (const float*)d_in[6];
    const float* w13 = (const float*)d_in[7];
    const float* b13 = (const float*)d_in[8];
    const float* cW  = (const float*)d_in[9];
    const float* cb  = (const float*)d_in[10];
    const float* w21 = (const float*)d_in[11];
    const float* b21 = (const float*)d_in[12];
    const float* w22 = (const float*)d_in[13];
    const float* b22 = (const float*)d_in[14];
    const float* w23 = (const float*)d_in[15];
    const float* b23 = (const float*)d_in[16];
    const float* gamma = (const float*)d_in[17];
    const float* beta  = (const float*)d_in[18];
    float* out = (float*)d_out;

    cudaFuncSetAttribute(tconv_kernel,
                         cudaFuncAttributeMaxDynamicSharedMemorySize, TC_SMEM);

    // 1: all prep
    prep_all_kernel<<<4, 1024>>>(ei, ew, w11, w12, w13, w21, w22, w23);

    // 2: tconv1
    {
        dim3 grid(Nv / 128, T1v, Bv);
        tconv_kernel<<<grid, 256, TC_SMEM>>>(x, b11, b12, b13, 0, 0, 0, Tv, T1v);
    }
    // 3: cheb GEMM (Y0, Y1)
    {
        dim3 grid(Nv / 128, T1v, Bv);
        cheb_gemm_kernel<<<grid, 256, CG_SMEM>>>(cW);
    }
    // 4: cheb gather (ncu window)
    {
        dim3 grid(Nv / 8, 16, Bv);
        cheb_gather_kernel<<<grid, 256>>>(cb);
    }
    // 5: tconv2
    {
        dim3 grid(Nv / 128, T2v, Bv);
        tconv_kernel<<<grid, 256, TC_SMEM>>>(x, b21, b22, b23, 1, 1, 1, T1v, T2v);
    }
    // 6: bn
    bn_kernel<<<Nv, 256>>>(gamma, beta, out);
}